// round 14
// baseline (speedup 1.0000x reference)
#include <cuda_runtime.h>
#include <cuda_fp16.h>
#include <cstdint>

// AnomalyAttention, sm_103, pure-fp16 HMMA, 128-row tile, 1 CTA/SM, 8 warps.
// r13 + fully-resident K (then V) in smem: 3 barriers total, barrier-free QK/AV.
// B=32 L=S=512 H=8 E=64.

#define Bn 32
#define Ln 512
#define Hn 8
#define En 64
#define Sn 512
#define HE (Hn*En)
#define TM 128

static constexpr size_t VOUT_ELEMS = (size_t)Bn * Ln * Hn * En;  // 8388608
static constexpr size_t SER_ELEMS  = (size_t)Bn * Hn * Ln * Sn;  // 67108864

// ---- smem layout (bytes) ----
#define Q_OFF   0        // 128x64 fp16 SW128 (16384)
#define K_OFF   16384    // 512x64 fp16 SW128 (65536): K, then V
#define P_OFF   81920    // 128 rows x 1024B fp16, swizzled (131072)
#define RS_OFF  212992   // rowsum partials [2][128] f32 (1024)
#define SMEM_BYTES 214016

#define SWZ(o) ((o) ^ ((((unsigned)(o)) >> 3) & 0x70u))
#define PADDR(row, b0) (P_OFF + (unsigned)(row) * 1024u + ((unsigned)(b0) & ~127u) \
                        + (((unsigned)(b0) & 127u) ^ (((unsigned)(row) & 7u) << 4)))

__device__ __forceinline__ uint32_t smem_u32(const void* p) {
    uint32_t a;
    asm("{ .reg .u64 t; cvta.to.shared.u64 t, %1; cvt.u32.u64 %0, t; }" : "=r"(a) : "l"(p));
    return a;
}
__device__ __forceinline__ void ldm_x4(uint32_t a, uint32_t r[4]) {
    asm volatile("ldmatrix.sync.aligned.m8n8.x4.shared.b16 {%0,%1,%2,%3}, [%4];"
        : "=r"(r[0]), "=r"(r[1]), "=r"(r[2]), "=r"(r[3]) : "r"(a));
}
__device__ __forceinline__ void ldm_x4t(uint32_t a, uint32_t r[4]) {
    asm volatile("ldmatrix.sync.aligned.m8n8.x4.trans.shared.b16 {%0,%1,%2,%3}, [%4];"
        : "=r"(r[0]), "=r"(r[1]), "=r"(r[2]), "=r"(r[3]) : "r"(a));
}
__device__ __forceinline__ void mma_f16(float c[4], const uint32_t a[4],
                                        uint32_t b0, uint32_t b1) {
    asm volatile("mma.sync.aligned.m16n8k16.row.col.f32.f16.f16.f32 "
        "{%0,%1,%2,%3}, {%4,%5,%6,%7}, {%8,%9}, {%0,%1,%2,%3};"
        : "+f"(c[0]), "+f"(c[1]), "+f"(c[2]), "+f"(c[3])
        : "r"(a[0]), "r"(a[1]), "r"(a[2]), "r"(a[3]), "r"(b0), "r"(b1));
}
__device__ __forceinline__ uint32_t pkh2(float lo, float hi) {
    __half2 t = __floats2half2_rn(lo, hi);
    return *reinterpret_cast<uint32_t*>(&t);
}
__device__ __forceinline__ float ex2f(float x) {
    float y; asm("ex2.approx.ftz.f32 %0, %1;" : "=f"(y) : "f"(x)); return y;
}

// register stage: 128B of f32 per thread (128x64 tile / 256 threads)
struct Stage { float4 s[8]; };
__device__ __forceinline__ void fetch128(const float* __restrict__ g, int tid, Stage& st) {
#pragma unroll
    for (int it = 0; it < 4; ++it) {
        int idx = tid + it * 256;
        int row = idx >> 3, cp = idx & 7;
        const float4* s = (const float4*)(g + (size_t)row * HE + cp * 8);
        st.s[2 * it]     = s[0];
        st.s[2 * it + 1] = s[1];
    }
}
__device__ __forceinline__ void commit128(char* sm, int tid, const Stage& st, unsigned off) {
#pragma unroll
    for (int it = 0; it < 4; ++it) {
        int idx = tid + it * 256;
        int row = idx >> 3, cp = idx & 7;
        float4 a = st.s[2 * it], b = st.s[2 * it + 1];
        uint4 o;
        o.x = pkh2(a.x, a.y); o.y = pkh2(a.z, a.w);
        o.z = pkh2(b.x, b.y); o.w = pkh2(b.z, b.w);
        unsigned rel = row * 128 + cp * 16;
        *(uint4*)(sm + off + SWZ(rel)) = o;
    }
}

__global__ __launch_bounds__(256, 1)
void anomaly_attn_r14(const float* __restrict__ Q, const float* __restrict__ K,
                      const float* __restrict__ V, const float* __restrict__ Sg,
                      float* __restrict__ out)
{
    extern __shared__ char sm[];
    const uint32_t smu = smem_u32(sm);
    float* RS = (float*)(sm + RS_OFF);

    const int tid  = threadIdx.x;
    const int wid  = tid >> 5;
    const int lane = tid & 31;
    const int g    = lane >> 2;
    const int t    = lane & 3;
    const int mw   = wid & 3;      // 32-row group
    const int nw   = wid >> 2;     // col half
    const int m0   = mw * 32;

    const int tile = blockIdx.x & 3;
    const int h    = (blockIdx.x >> 2) & 7;
    const int b    = blockIdx.x >> 5;
    const int l0   = tile * TM;

    const size_t qkv = ((size_t)b * Ln) * HE + (size_t)h * En;
    const size_t rowBaseSP = (size_t)(b * Hn + h) * Ln + l0;
    const uint32_t ONES = 0x3C003C00u;   // half2(1.0, 1.0)

    // ---- Phase A: Q (scaled by log2e/8) + ALL of K -> fp16 smem ----
    const float QS = 0.125f * 1.44269504088896340736f;
#pragma unroll
    for (int it = 0; it < 4; ++it) {
        int idx = tid + it * 256;
        int row = idx >> 3, cp = idx & 7;
        const float4* s = (const float4*)(Q + qkv + (size_t)(l0 + row) * HE + cp * 8);
        float4 a = s[0], bq = s[1];
        uint4 o;
        o.x = pkh2(a.x * QS, a.y * QS);
        o.y = pkh2(a.z * QS, a.w * QS);
        o.z = pkh2(bq.x * QS, bq.y * QS);
        o.w = pkh2(bq.z * QS, bq.w * QS);
        unsigned rel = row * 128 + cp * 16;
        *(uint4*)(sm + Q_OFF + SWZ(rel)) = o;
    }
#pragma unroll
    for (int it = 0; it < 16; ++it) {
        int idx = tid + it * 256;
        int row = idx >> 3, cp = idx & 7;
        const float4* s = (const float4*)(K + qkv + (size_t)row * HE + cp * 8);
        float4 a = s[0], bq = s[1];
        uint4 o;
        o.x = pkh2(a.x, a.y); o.y = pkh2(a.z, a.w);
        o.z = pkh2(bq.x, bq.y); o.w = pkh2(bq.z, bq.w);
        unsigned rel = row * 128 + cp * 16;
        *(uint4*)(sm + K_OFF + SWZ(rel)) = o;
    }
    __syncthreads();   // sync1

    // ---- Q A-fragments: 2 row-tiles x 4 k-steps ----
    uint32_t aq[2][4][4];
#pragma unroll
    for (int mt = 0; mt < 2; ++mt) {
        int r = m0 + mt * 16 + (lane & 15);
        int ch = lane >> 4;
#pragma unroll
        for (int kk = 0; kk < 4; ++kk) {
            unsigned rel = (unsigned)r * 128 + kk * 32 + ch * 16;
            ldm_x4(smu + Q_OFF + SWZ(rel), aq[mt][kk]);
        }
    }

    // ---- QK^T: barrier-free; warp owns 32 rows x 64-col half per chunk ----
    Stage st;
    float rsacc[2][4] = { {0.f,0.f,0.f,0.f}, {0.f,0.f,0.f,0.f} };
#pragma unroll 1
    for (int c = 0; c < 4; ++c) {
        if (c == 2) fetch128(V + qkv, tid, st);    // stage V chunk 0
        const uint32_t kbase = smu + K_OFF + (unsigned)c * 16384;

        float acc[2][8][4];
#pragma unroll
        for (int mt = 0; mt < 2; ++mt)
#pragma unroll
            for (int i = 0; i < 8; ++i) { acc[mt][i][0]=0.f; acc[mt][i][1]=0.f; acc[mt][i][2]=0.f; acc[mt][i][3]=0.f; }
#pragma unroll
        for (int kk = 0; kk < 4; ++kk) {
#pragma unroll
            for (int jj = 0; jj < 4; ++jj) {
                uint32_t bh[4];
                int r = nw * 64 + jj * 16 + (lane & 15);
                unsigned rel = (unsigned)r * 128 + kk * 32 + (lane >> 4) * 16;
                ldm_x4(kbase + SWZ(rel), bh);
                mma_f16(acc[0][2 * jj],     aq[0][kk], bh[0], bh[2]);
                mma_f16(acc[0][2 * jj + 1], aq[0][kk], bh[1], bh[3]);
                mma_f16(acc[1][2 * jj],     aq[1][kk], bh[0], bh[2]);
                mma_f16(acc[1][2 * jj + 1], aq[1][kk], bh[1], bh[3]);
            }
        }
#pragma unroll
        for (int mt = 0; mt < 2; ++mt) {
            int row0 = m0 + mt * 16 + g, row1 = row0 + 8;
#pragma unroll
            for (int j = 0; j < 4; ++j) {
                float eA0 = ex2f(acc[mt][2*j][0]),   eA1 = ex2f(acc[mt][2*j][1]);
                float eA2 = ex2f(acc[mt][2*j][2]),   eA3 = ex2f(acc[mt][2*j][3]);
                float eB0 = ex2f(acc[mt][2*j+1][0]), eB1 = ex2f(acc[mt][2*j+1][1]);
                float eB2 = ex2f(acc[mt][2*j+1][2]), eB3 = ex2f(acc[mt][2*j+1][3]);
                uint32_t hA01 = pkh2(eA0, eA1), hA23 = pkh2(eA2, eA3);
                uint32_t hB01 = pkh2(eB0, eB1), hB23 = pkh2(eB2, eB3);
                unsigned bA = (unsigned)(c * 128 + nw * 64 + j * 16 + 2 * t) * 2;
                *(uint32_t*)(sm + PADDR(row0, bA))      = hA01;
                *(uint32_t*)(sm + PADDR(row1, bA))      = hA23;
                *(uint32_t*)(sm + PADDR(row0, bA + 16)) = hB01;
                *(uint32_t*)(sm + PADDR(row1, bA + 16)) = hB23;
                uint32_t af[4] = { hA01, hA23, hB01, hB23 };
                mma_f16(rsacc[mt], af, ONES, ONES);
            }
        }
    }

    // rowsum partials -> smem
    if (t == 0) {
        RS[nw * 128 + m0 + g]      = rsacc[0][0];
        RS[nw * 128 + m0 + 8 + g]  = rsacc[0][2];
        RS[nw * 128 + m0 + 16 + g] = rsacc[1][0];
        RS[nw * 128 + m0 + 24 + g] = rsacc[1][2];
    }
    __syncthreads();   // sync2: P complete, K dead, RS ready

    float inv[4];
#pragma unroll
    for (int mt = 0; mt < 2; ++mt) {
        int r0 = m0 + mt * 16 + g;
        inv[2 * mt]     = 1.0f / (RS[r0] + RS[128 + r0]);
        inv[2 * mt + 1] = 1.0f / (RS[r0 + 8] + RS[128 + r0 + 8]);
    }

    // ---- V fill: chunk 0 from staged regs, chunks 1-3 direct ----
    commit128(sm, tid, st, K_OFF);
#pragma unroll
    for (int it = 0; it < 12; ++it) {
        int idx = tid + it * 256;
        int row = 128 + (idx >> 3), cp = idx & 7;
        const float4* s = (const float4*)(V + qkv + (size_t)row * HE + cp * 8);
        float4 a = s[0], bq = s[1];
        uint4 o;
        o.x = pkh2(a.x, a.y); o.y = pkh2(a.z, a.w);
        o.z = pkh2(bq.x, bq.y); o.w = pkh2(bq.z, bq.w);
        unsigned rel = row * 128 + cp * 16;
        *(uint4*)(sm + K_OFF + SWZ(rel)) = o;
    }
    __syncthreads();   // sync3: V resident

    // ---- AV: barrier-free; warp: 32 rows x 32 E-cols; series fused ----
    float* serB = out + VOUT_ELEMS;
    float* sr[4];
#pragma unroll
    for (int mt = 0; mt < 2; ++mt) {
        sr[2 * mt]     = serB + (rowBaseSP + m0 + mt * 16 + g) * (size_t)Sn;
        sr[2 * mt + 1] = serB + (rowBaseSP + m0 + mt * 16 + 8 + g) * (size_t)Sn;
    }

    float oacc[2][4][4];
#pragma unroll
    for (int mt = 0; mt < 2; ++mt)
#pragma unroll
        for (int i = 0; i < 4; ++i) { oacc[mt][i][0]=0.f; oacc[mt][i][1]=0.f; oacc[mt][i][2]=0.f; oacc[mt][i][3]=0.f; }
#pragma unroll 1
    for (int c = 0; c < 4; ++c) {
        const uint32_t vbase = smu + K_OFF + (unsigned)c * 16384;
#pragma unroll
        for (int kl = 0; kl < 8; ++kl) {
            int ks = c * 8 + kl;
            uint32_t af[2][4];
#pragma unroll
            for (int mt = 0; mt < 2; ++mt)
                ldm_x4(smu + PADDR(m0 + mt * 16 + (lane & 15), ks * 32 + (lane >> 4) * 16), af[mt]);
            if ((ks & 1) == nw) {
                int colA = ks * 16 + 2 * t;
#pragma unroll
                for (int mt = 0; mt < 2; ++mt) {
                    __half2 h0 = *reinterpret_cast<__half2*>(&af[mt][0]);
                    __half2 h1 = *reinterpret_cast<__half2*>(&af[mt][1]);
                    __half2 h2 = *reinterpret_cast<__half2*>(&af[mt][2]);
                    __half2 h3 = *reinterpret_cast<__half2*>(&af[mt][3]);
                    float iv0 = inv[2 * mt], iv1 = inv[2 * mt + 1];
                    float2 o;
                    o.x = __half2float(h0.x) * iv0; o.y = __half2float(h0.y) * iv0;
                    *(float2*)(sr[2 * mt] + colA) = o;
                    o.x = __half2float(h1.x) * iv1; o.y = __half2float(h1.y) * iv1;
                    *(float2*)(sr[2 * mt + 1] + colA) = o;
                    o.x = __half2float(h2.x) * iv0; o.y = __half2float(h2.y) * iv0;
                    *(float2*)(sr[2 * mt] + colA + 8) = o;
                    o.x = __half2float(h3.x) * iv1; o.y = __half2float(h3.y) * iv1;
                    *(float2*)(sr[2 * mt + 1] + colA + 8) = o;
                }
            }
#pragma unroll
            for (int et = 0; et < 2; ++et) {
                uint32_t bh[4];
                int s = kl * 16 + (lane & 15);
                unsigned rel = (unsigned)s * 128 + nw * 64 + et * 32 + (lane >> 4) * 16;
                ldm_x4t(vbase + SWZ(rel), bh);
                mma_f16(oacc[0][2 * et],     af[0], bh[0], bh[1]);
                mma_f16(oacc[0][2 * et + 1], af[0], bh[2], bh[3]);
                mma_f16(oacc[1][2 * et],     af[1], bh[0], bh[1]);
                mma_f16(oacc[1][2 * et + 1], af[1], bh[2], bh[3]);
            }
        }
    }

    // ---- V_out = oacc * inv, layout [B,L,H,E]; warp's 32 E-cols at nw*32 ----
    {
#pragma unroll
        for (int mt = 0; mt < 2; ++mt) {
            float iv0 = inv[2 * mt], iv1 = inv[2 * mt + 1];
            float* o0 = out + (((size_t)(b * Ln + l0 + m0 + mt * 16 + g)) * Hn + h) * En + nw * 32;
            float* o1 = out + (((size_t)(b * Ln + l0 + m0 + mt * 16 + 8 + g)) * Hn + h) * En + nw * 32;
#pragma unroll
            for (int k = 0; k < 4; ++k) {
                int e = k * 8 + 2 * t;
                float2 v0 = { oacc[mt][k][0] * iv0, oacc[mt][k][1] * iv0 };
                float2 v1 = { oacc[mt][k][2] * iv1, oacc[mt][k][3] * iv1 };
                *(float2*)(o0 + e) = v0;
                *(float2*)(o1 + e) = v1;
            }
        }
    }

    // ---- prior tail with band window (rows wid*16 .. +15) ----
    {
        const int m0p = wid * 16;
        float sigl = 1.f;
        if (lane < 16) {
            float x = Sg[(size_t)(b * Ln + l0 + m0p + lane) * Hn + h];
            double sgm = 1.0 / (1.0 + exp(-5.0 * (double)x));
            float sgf = (float)sgm + 1e-5f;
            float p3 = (float)exp((double)sgf * 1.0986122886681098);
            sigl = p3 - 1.0f;
        }
        const double s2pi_d = 2.506628274631000502415765284811;
        const float  s2pi_f = (float)s2pi_d;
        const float  inv_sqrt_2pi = (float)(1.0 / (double)s2pi_f);
        float* priB = out + VOUT_ELEMS + SER_ELEMS;
        const float4 z4 = { 0.f, 0.f, 0.f, 0.f };
#pragma unroll 1
        for (int rr = 0; rr < 16; ++rr) {
            int row = m0p + rr;
            float sig = __shfl_sync(0xffffffffu, sigl, rr);
            float amp = inv_sqrt_2pi / sig;
            float nb  = -0.5f / (sig * sig);
            float nb2 = nb * 1.44269504088896340736f;
            int l = l0 + row;
            float* prow = priB + (rowBaseSP + row) * (size_t)Sn;

            int ws = l - 64;
            ws = ws < 0 ? 0 : (ws > 384 ? 384 : ws);
            ws &= ~3;

            int colz = lane * 4;
            if (colz < ws || colz >= ws + 128)
                *(float4*)(prow + colz) = z4;

            int s0 = ws + lane * 4;
            float d0 = (float)(l - s0);
            float4 o;
            o.x = amp * ex2f(nb2 * d0 * d0);
            float d1 = d0 - 1.f;
            o.y = amp * ex2f(nb2 * d1 * d1);
            float d2 = d0 - 2.f;
            o.z = amp * ex2f(nb2 * d2 * d2);
            float d3 = d0 - 3.f;
            o.w = amp * ex2f(nb2 * d3 * d3);
            *(float4*)(prow + s0) = o;
        }
    }
}

extern "C" void kernel_launch(void* const* d_in, const int* in_sizes, int n_in,
                              void* d_out, int out_size)
{
    const float* Q  = (const float*)d_in[0];
    const float* K  = (const float*)d_in[1];
    const float* V  = (const float*)d_in[2];
    const float* Sg = (const float*)d_in[3];
    float* out = (float*)d_out;

    cudaFuncSetAttribute(anomaly_attn_r14,
                         cudaFuncAttributeMaxDynamicSharedMemorySize, SMEM_BYTES);
    dim3 grid(Bn * Hn * (Ln / TM));   // 1024 CTAs
    anomaly_attn_r14<<<grid, 256, SMEM_BYTES>>>(Q, K, V, Sg, out);
}

// round 16
// speedup vs baseline: 1.0812x; 1.0812x over previous
#include <cuda_runtime.h>
#include <cuda_fp16.h>
#include <cstdint>

// AnomalyAttention, sm_103, pure-fp16 HMMA, 128-row tile, 1 CTA/SM, 8 warps.
// Flash-style fusion: QK accumulator (exp'd, packed fp16) is used directly as
// the AV MMA A-operand in registers; QK+AV in ONE chunk loop; P smem kept only
// for the series epilogue (linear LDS + coalesced STG.128).
// B=32 L=S=512 H=8 E=64.

#define Bn 32
#define Ln 512
#define Hn 8
#define En 64
#define Sn 512
#define HE (Hn*En)
#define TM 128

static constexpr size_t VOUT_ELEMS = (size_t)Bn * Ln * Hn * En;  // 8388608
static constexpr size_t SER_ELEMS  = (size_t)Bn * Hn * Ln * Sn;  // 67108864

// ---- smem layout (bytes) ----
#define Q_OFF   0        // 128x64 fp16 SW128 (16384)
#define KV_OFF  16384    // 2 bufs x (K 16K + V 16K) = 65536
#define P_OFF   81920    // 128 rows x 1024B fp16, swizzled (131072)
#define SMEM_BYTES 212992

#define SWZ(o) ((o) ^ ((((unsigned)(o)) >> 3) & 0x70u))
#define PADDR(row, b0) (P_OFF + (unsigned)(row) * 1024u + ((unsigned)(b0) & ~127u) \
                        + (((unsigned)(b0) & 127u) ^ (((unsigned)(row) & 7u) << 4)))

__device__ __forceinline__ uint32_t smem_u32(const void* p) {
    uint32_t a;
    asm("{ .reg .u64 t; cvta.to.shared.u64 t, %1; cvt.u32.u64 %0, t; }" : "=r"(a) : "l"(p));
    return a;
}
__device__ __forceinline__ void ldm_x4(uint32_t a, uint32_t r[4]) {
    asm volatile("ldmatrix.sync.aligned.m8n8.x4.shared.b16 {%0,%1,%2,%3}, [%4];"
        : "=r"(r[0]), "=r"(r[1]), "=r"(r[2]), "=r"(r[3]) : "r"(a));
}
__device__ __forceinline__ void ldm_x4t(uint32_t a, uint32_t r[4]) {
    asm volatile("ldmatrix.sync.aligned.m8n8.x4.trans.shared.b16 {%0,%1,%2,%3}, [%4];"
        : "=r"(r[0]), "=r"(r[1]), "=r"(r[2]), "=r"(r[3]) : "r"(a));
}
__device__ __forceinline__ void mma_f16(float c[4], const uint32_t a[4],
                                        uint32_t b0, uint32_t b1) {
    asm volatile("mma.sync.aligned.m16n8k16.row.col.f32.f16.f16.f32 "
        "{%0,%1,%2,%3}, {%4,%5,%6,%7}, {%8,%9}, {%0,%1,%2,%3};"
        : "+f"(c[0]), "+f"(c[1]), "+f"(c[2]), "+f"(c[3])
        : "r"(a[0]), "r"(a[1]), "r"(a[2]), "r"(a[3]), "r"(b0), "r"(b1));
}
__device__ __forceinline__ uint32_t pkh2(float lo, float hi) {
    __half2 t = __floats2half2_rn(lo, hi);
    return *reinterpret_cast<uint32_t*>(&t);
}
__device__ __forceinline__ float ex2f(float x) {
    float y; asm("ex2.approx.ftz.f32 %0, %1;" : "=f"(y) : "f"(x)); return y;
}

// register stage: 128B of f32 per thread (128x64 tile / 256 threads)
struct Stage { float4 s[8]; };
__device__ __forceinline__ void fetch128(const float* __restrict__ g, int tid, Stage& st) {
#pragma unroll
    for (int it = 0; it < 4; ++it) {
        int idx = tid + it * 256;
        int row = idx >> 3, cp = idx & 7;
        const float4* s = (const float4*)(g + (size_t)row * HE + cp * 8);
        st.s[2 * it]     = s[0];
        st.s[2 * it + 1] = s[1];
    }
}
__device__ __forceinline__ void commit128(char* sm, int tid, const Stage& st, unsigned off) {
#pragma unroll
    for (int it = 0; it < 4; ++it) {
        int idx = tid + it * 256;
        int row = idx >> 3, cp = idx & 7;
        float4 a = st.s[2 * it], b = st.s[2 * it + 1];
        uint4 o;
        o.x = pkh2(a.x, a.y); o.y = pkh2(a.z, a.w);
        o.z = pkh2(b.x, b.y); o.w = pkh2(b.z, b.w);
        unsigned rel = row * 128 + cp * 16;
        *(uint4*)(sm + off + SWZ(rel)) = o;
    }
}

__global__ __launch_bounds__(256, 1)
void anomaly_attn_r15(const float* __restrict__ Q, const float* __restrict__ K,
                      const float* __restrict__ V, const float* __restrict__ Sg,
                      float* __restrict__ out)
{
    extern __shared__ char sm[];
    const uint32_t smu = smem_u32(sm);

    const int tid  = threadIdx.x;
    const int wid  = tid >> 5;
    const int lane = tid & 31;
    const int g    = lane >> 2;
    const int t    = lane & 3;
    const int m0   = wid * 16;

    const int tile = blockIdx.x & 3;
    const int h    = (blockIdx.x >> 2) & 7;
    const int b    = blockIdx.x >> 5;
    const int l0   = tile * TM;

    const size_t qkv = ((size_t)b * Ln) * HE + (size_t)h * En;
    const size_t rowBaseSP = (size_t)(b * Hn + h) * Ln + l0;
    const uint32_t ONES = 0x3C003C00u;   // half2(1.0, 1.0)

    // ---- Q load -> fp16 smem, pre-scaled by (1/8)*log2(e) ----
    const float QS = 0.125f * 1.44269504088896340736f;
#pragma unroll
    for (int it = 0; it < 4; ++it) {
        int idx = tid + it * 256;
        int row = idx >> 3, cp = idx & 7;
        const float4* s = (const float4*)(Q + qkv + (size_t)(l0 + row) * HE + cp * 8);
        float4 a = s[0], bq = s[1];
        uint4 o;
        o.x = pkh2(a.x * QS, a.y * QS);
        o.y = pkh2(a.z * QS, a.w * QS);
        o.z = pkh2(bq.x * QS, bq.y * QS);
        o.w = pkh2(bq.z * QS, bq.w * QS);
        unsigned rel = row * 128 + cp * 16;
        *(uint4*)(sm + Q_OFF + SWZ(rel)) = o;
    }

    // buffer base: buf i -> KV_OFF + i*32768 (+0 = K, +16384 = V)
    Stage st;
    fetch128(K + qkv, tid, st);
    commit128(sm, tid, st, KV_OFF + 0);             // K0 -> buf0.K
    fetch128(V + qkv, tid, st);
    commit128(sm, tid, st, KV_OFF + 16384);         // V0 -> buf0.V
    fetch128(K + qkv + (size_t)128 * HE, tid, st);  // K1 staged
    __syncthreads();   // sync1

    // ---- Q A-fragments ----
    uint32_t aq[4][4];
    {
        int r = m0 + (lane & 15);
        int ch = lane >> 4;
#pragma unroll
        for (int kk = 0; kk < 4; ++kk) {
            unsigned rel = (unsigned)r * 128 + kk * 32 + ch * 16;
            ldm_x4(smu + Q_OFF + SWZ(rel), aq[kk]);
        }
    }

    // ---- fused QK+AV chunk loop ----
    float rsacc[4] = { 0.f, 0.f, 0.f, 0.f };
    float oacc[8][4];
#pragma unroll
    for (int i = 0; i < 8; ++i) { oacc[i][0]=0.f; oacc[i][1]=0.f; oacc[i][2]=0.f; oacc[i][3]=0.f; }

#pragma unroll 1
    for (int c = 0; c < 4; ++c) {
        if (c < 3) {
            commit128(sm, tid, st, KV_OFF + ((c + 1) & 1) * 32768);          // K(c+1)
            fetch128(V + qkv + (size_t)((c + 1) * 128) * HE, tid, st);       // stage V(c+1)
        }
        const uint32_t kbase = smu + KV_OFF + (unsigned)(c & 1) * 32768;
        const uint32_t vbase = kbase + 16384;

        // --- QK MMAs: 16 rows x 128 cols of this chunk ---
        float acc[16][4];
#pragma unroll
        for (int i = 0; i < 16; ++i) { acc[i][0]=0.f; acc[i][1]=0.f; acc[i][2]=0.f; acc[i][3]=0.f; }
#pragma unroll
        for (int kk = 0; kk < 4; ++kk) {
#pragma unroll
            for (int jj = 0; jj < 8; ++jj) {
                uint32_t bh[4];
                int r = jj * 16 + (lane & 15);
                unsigned rel = (unsigned)r * 128 + kk * 32 + (lane >> 4) * 16;
                ldm_x4(kbase + SWZ(rel), bh);
                mma_f16(acc[2 * jj],     aq[kk], bh[0], bh[2]);
                mma_f16(acc[2 * jj + 1], aq[kk], bh[1], bh[3]);
            }
        }

        // --- softmax numerators: ex2 -> fp16 A-fragments; STS for series; rowsum MMA ---
        uint32_t af[8][4];
        int row0 = m0 + g, row1 = m0 + 8 + g;
#pragma unroll
        for (int kl = 0; kl < 8; ++kl) {
            af[kl][0] = pkh2(ex2f(acc[2*kl][0]),   ex2f(acc[2*kl][1]));
            af[kl][1] = pkh2(ex2f(acc[2*kl][2]),   ex2f(acc[2*kl][3]));
            af[kl][2] = pkh2(ex2f(acc[2*kl+1][0]), ex2f(acc[2*kl+1][1]));
            af[kl][3] = pkh2(ex2f(acc[2*kl+1][2]), ex2f(acc[2*kl+1][3]));
            unsigned colb = (unsigned)(c * 128 + kl * 16 + 2 * t) * 2;
            *(uint32_t*)(sm + PADDR(row0, colb))      = af[kl][0];
            *(uint32_t*)(sm + PADDR(row1, colb))      = af[kl][1];
            *(uint32_t*)(sm + PADDR(row0, colb + 16)) = af[kl][2];
            *(uint32_t*)(sm + PADDR(row1, colb + 16)) = af[kl][3];
            mma_f16(rsacc, af[kl], ONES, ONES);
        }

        // --- AV MMAs: af (registers!) x V chunk ---
#pragma unroll
        for (int kl = 0; kl < 8; ++kl) {
#pragma unroll
            for (int et = 0; et < 4; ++et) {
                uint32_t bh[4];
                int s = kl * 16 + (lane & 15);
                unsigned rel = (unsigned)s * 128 + et * 32 + (lane >> 4) * 16;
                ldm_x4t(vbase + SWZ(rel), bh);
                mma_f16(oacc[2 * et],     af[kl], bh[0], bh[1]);
                mma_f16(oacc[2 * et + 1], af[kl], bh[2], bh[3]);
            }
        }

        if (c < 3) {
            commit128(sm, tid, st, KV_OFF + ((c + 1) & 1) * 32768 + 16384); // V(c+1)
            if (c < 2) fetch128(K + qkv + (size_t)((c + 2) * 128) * HE, tid, st);
            __syncthreads();
        }
    }

    const float inv0 = 1.0f / rsacc[0];   // row m0+g
    const float inv1 = 1.0f / rsacc[2];   // row m0+8+g

    // ---- V_out = oacc * inv, layout [B,L,H,E] ----
    {
        float* o0 = out + (((size_t)(b * Ln + l0 + m0 + g)) * Hn + h) * En;
        float* o1 = out + (((size_t)(b * Ln + l0 + m0 + 8 + g)) * Hn + h) * En;
#pragma unroll
        for (int k = 0; k < 8; ++k) {
            int e = k * 8 + 2 * t;
            float2 v0 = { oacc[k][0] * inv0, oacc[k][1] * inv0 };
            float2 v1 = { oacc[k][2] * inv1, oacc[k][3] * inv1 };
            *(float2*)(o0 + e) = v0;
            *(float2*)(o1 + e) = v1;
        }
    }

    // ---- series epilogue: linear P read (LDS.64) -> coalesced STG.128 ----
    {
        float* serB = out + VOUT_ELEMS;
#pragma unroll 1
        for (int rr = 0; rr < 16; ++rr) {
            int row = m0 + rr;
            float iv = (rr < 8) ? __shfl_sync(0xffffffffu, inv0, 4 * rr)
                                : __shfl_sync(0xffffffffu, inv1, 4 * (rr - 8));
            float* srow = serB + (rowBaseSP + row) * (size_t)Sn;
#pragma unroll
            for (int p = 0; p < 4; ++p) {
                unsigned b0 = 8u * lane + 256u * p;       // 4 halves per lane
                uint2 hv = *(uint2*)(sm + PADDR(row, b0));
                __half2 ha = *reinterpret_cast<__half2*>(&hv.x);
                __half2 hb = *reinterpret_cast<__half2*>(&hv.y);
                float4 o;
                o.x = __half2float(ha.x) * iv;
                o.y = __half2float(ha.y) * iv;
                o.z = __half2float(hb.x) * iv;
                o.w = __half2float(hb.y) * iv;
                *(float4*)(srow + 4 * lane + 128 * p) = o;
            }
        }
    }

    // ---- prior tail with band window (rows m0..m0+15) ----
    {
        float sigl = 1.f;
        if (lane < 16) {
            float x = Sg[(size_t)(b * Ln + l0 + m0 + lane) * Hn + h];
            double sgm = 1.0 / (1.0 + exp(-5.0 * (double)x));
            float sgf = (float)sgm + 1e-5f;
            float p3 = (float)exp((double)sgf * 1.0986122886681098);
            sigl = p3 - 1.0f;
        }
        const double s2pi_d = 2.506628274631000502415765284811;
        const float  s2pi_f = (float)s2pi_d;
        const float  inv_sqrt_2pi = (float)(1.0 / (double)s2pi_f);
        float* priB = out + VOUT_ELEMS + SER_ELEMS;
        const float4 z4 = { 0.f, 0.f, 0.f, 0.f };
#pragma unroll 1
        for (int rr = 0; rr < 16; ++rr) {
            int row = m0 + rr;
            float sig = __shfl_sync(0xffffffffu, sigl, rr);
            float amp = inv_sqrt_2pi / sig;
            float nb  = -0.5f / (sig * sig);
            float nb2 = nb * 1.44269504088896340736f;
            int l = l0 + row;
            float* prow = priB + (rowBaseSP + row) * (size_t)Sn;

            int ws = l - 64;
            ws = ws < 0 ? 0 : (ws > 384 ? 384 : ws);
            ws &= ~3;

            int colz = lane * 4;
            if (colz < ws || colz >= ws + 128)
                *(float4*)(prow + colz) = z4;

            int s0 = ws + lane * 4;
            float d0 = (float)(l - s0);
            float4 o;
            o.x = amp * ex2f(nb2 * d0 * d0);
            float d1 = d0 - 1.f;
            o.y = amp * ex2f(nb2 * d1 * d1);
            float d2 = d0 - 2.f;
            o.z = amp * ex2f(nb2 * d2 * d2);
            float d3 = d0 - 3.f;
            o.w = amp * ex2f(nb2 * d3 * d3);
            *(float4*)(prow + s0) = o;
        }
    }
}

extern "C" void kernel_launch(void* const* d_in, const int* in_sizes, int n_in,
                              void* d_out, int out_size)
{
    const float* Q  = (const float*)d_in[0];
    const float* K  = (const float*)d_in[1];
    const float* V  = (const float*)d_in[2];
    const float* Sg = (const float*)d_in[3];
    float* out = (float*)d_out;

    cudaFuncSetAttribute(anomaly_attn_r15,
                         cudaFuncAttributeMaxDynamicSharedMemorySize, SMEM_BYTES);
    dim3 grid(Bn * Hn * (Ln / TM));   // 1024 CTAs
    anomaly_attn_r15<<<grid, 256, SMEM_BYTES>>>(Q, K, V, Sg, out);
}